// round 1
// baseline (speedup 1.0000x reference)
#include <cuda_runtime.h>

#define RES     96
#define CENTERF 48.0f
#define EPSF    1e-5f
#define CAP     6144   // compacted-source capacity staged in SMEM (expected K ~ 4608)

// Scratch (no cudaMalloc allowed): compacted source list + count.
__device__ float4 g_entries[RES * RES];
__device__ int    g_count;

// ---------------------------------------------------------------------------
// Kernel A: deterministic compaction of strictly-positive boundary values.
// 1 block, 1024 threads. 32 warps, 3 rows each; ballot-based intra-row scan,
// serial cross-row prefix by thread 0. Output order is (row, col) ascending,
// so downstream summation order is identical on every call.
// ---------------------------------------------------------------------------
__global__ void compact_kernel(const float* __restrict__ b) {
    __shared__ int cnts[RES];
    __shared__ int offs[RES];
    const int tid  = threadIdx.x;
    const int wid  = tid >> 5;
    const int lane = tid & 31;

    // Pass 1: per-row positive counts
    for (int r = wid; r < RES; r += 32) {
        int c = 0;
        #pragma unroll
        for (int s = 0; s < 3; s++) {
            float v = b[r * RES + s * 32 + lane];
            unsigned m = __ballot_sync(0xffffffffu, v > 0.0f);
            c += __popc(m);
        }
        if (lane == 0) cnts[r] = c;
    }
    __syncthreads();

    if (tid == 0) {
        int s = 0;
        #pragma unroll 1
        for (int r = 0; r < RES; r++) { offs[r] = s; s += cnts[r]; }
        g_count = s;
    }
    __syncthreads();

    // Pass 2: write compacted entries at deterministic positions
    for (int r = wid; r < RES; r += 32) {
        int p = offs[r];
        #pragma unroll
        for (int s = 0; s < 3; s++) {
            int col = s * 32 + lane;
            float v = b[r * RES + col];
            unsigned m = __ballot_sync(0xffffffffu, v > 0.0f);
            if (v > 0.0f) {
                int pos = p + __popc(m & ((1u << lane) - 1u));
                g_entries[pos] = make_float4((float)r, (float)col, v, 0.0f);
            }
            p += __popc(m);
        }
    }
}

// ---------------------------------------------------------------------------
// Kernel B: potential evaluation.
// Grid: 288 blocks = 96 target rows x 3 j-groups of 32.
// Block: 256 threads = 32 lanes (consecutive j) x 8 source chunks.
// Source list staged in dynamic SMEM; all lanes of a warp read the same
// entry per iteration (broadcast LDS.128). Per entry:
//   di = fi - bi; dj = fj - bj;
//   denom = fma(dj,dj, fma(di,di, z^2 + eps^2));   // exact-int d2 path
//   acc  += w * rcp.approx(denom);
// The 2*eps*sqrt(d2) cross term is dropped (rel contribution <= eps/z <= 1e-5).
// ---------------------------------------------------------------------------
__global__ void __launch_bounds__(256) potential_kernel(
    const float* __restrict__ b, float* __restrict__ out)
{
    extern __shared__ float4 sm[];
    __shared__ float red[256];

    const int bx    = blockIdx.x;
    const int i     = bx / 3;
    const int jb    = (bx % 3) * 32;
    const int lane  = threadIdx.x & 31;
    const int chunk = threadIdx.x >> 5;       // 0..7
    const int j     = jb + lane;

    const int K  = g_count;
    const int KS = K < CAP ? K : CAP;
    for (int t = threadIdx.x; t < KS; t += 256) sm[t] = g_entries[t];
    __syncthreads();

    const float fi  = (float)i;
    const float fj  = (float)j;
    const float dic = fi - CENTERF;
    const float djc = fj - CENTERF;
    const float r2  = dic * dic + djc * djc;   // exact integer-valued float
    const float r   = sqrtf(r2);
    const float z   = CENTERF - r + EPSF;
    const float c0  = fmaf(z, z, EPSF * EPSF);

    float acc0 = 0.0f, acc1 = 0.0f;

    // Skip warps whose 32 targets are all rim (their output is a passthrough).
    const bool all_rim = __all_sync(0xffffffffu, r2 >= 2209.0f);
    if (!all_rim) {
        int idx = chunk;
        #pragma unroll 4
        for (; idx < KS; idx += 8) {
            float4 e = sm[idx];
            float di = fi - e.x;
            float dj = fj - e.y;
            float t  = fmaf(di, di, c0);
            float denom = fmaf(dj, dj, t);
            float inv;
            asm("rcp.approx.ftz.f32 %0, %1;" : "=f"(inv) : "f"(denom));
            acc0 = fmaf(e.z, inv, acc0);
        }
        // Overflow tail straight from global (empty unless K > CAP).
        for (int t2 = CAP + chunk; t2 < K; t2 += 8) {
            float4 e = g_entries[t2];
            float di = fi - e.x;
            float dj = fj - e.y;
            float t  = fmaf(di, di, c0);
            float denom = fmaf(dj, dj, t);
            float inv;
            asm("rcp.approx.ftz.f32 %0, %1;" : "=f"(inv) : "f"(denom));
            acc1 = fmaf(e.z, inv, acc1);
        }
    }

    red[threadIdx.x] = acc0 + acc1;
    __syncthreads();

    if (chunk == 0) {
        float tot = 0.0f;
        #pragma unroll
        for (int c = 0; c < 8; c++) tot += red[c * 32 + lane];
        float bv = b[i * RES + j];
        out[i * RES + j] = (r2 >= 2209.0f) ? bv : tot;
    }
}

// ---------------------------------------------------------------------------
extern "C" void kernel_launch(void* const* d_in, const int* in_sizes, int n_in,
                              void* d_out, int out_size) {
    (void)in_sizes; (void)n_in; (void)out_size;
    const float* b   = (const float*)d_in[0];
    float*       out = (float*)d_out;

    const int smem_bytes = CAP * (int)sizeof(float4);  // 98304
    cudaFuncSetAttribute(potential_kernel,
                         cudaFuncAttributeMaxDynamicSharedMemorySize, smem_bytes);

    compact_kernel<<<1, 1024>>>(b);
    potential_kernel<<<288, 256, smem_bytes>>>(b, out);
}

// round 2
// speedup vs baseline: 1.4820x; 1.4820x over previous
#include <cuda_runtime.h>

#define RES     96
#define CENTERF 48.0f
#define EPSF    1e-5f
#define CAP     (RES * RES)          // 9216 — overflow impossible
#define NWARPS  32                   // 1024 threads/block
#define RIM2    2209.0f              // (center-1)^2 = 47^2, exact in fp32

// ---------------------------------------------------------------------------
// Single fused kernel.
// Grid: 144 blocks = 48 i-pairs x 3 j-groups. Block: 1024 threads (32 warps).
// Phase 1: per-block deterministic ballot compaction of strictly-positive
//          boundary values into SMEM as float4 (bi, bj, w, pad), (row,col)
//          ascending order -> deterministic summation order.
// Phase 2: each warp owns the block's 64-target tile (2 i-rows x 32 j-lanes)
//          and iterates a 1/32 stride of the source list. Per source, per lane:
//            dj   = fj - bj                       (exact int)
//            di0  = fi0 - bi                      (exact int)
//            s0   = fma(dj,dj, c00)               (no cancellation)
//            den0 = fma(di0,di0, s0)
//            t    = fma(di0, 2, Kc)               Kc = 1 + (z1^2 - z0^2), fp64-precomputed
//            den1 = den0 + t                      (== di1^2 + dj^2 + c01)
//            acc{0,1} += w * rcp.approx(den{0,1})
//          8 FMA-pipe + 2 MUFU + 1 broadcast LDS.128 per 2 terms.
//          The 2*eps*sqrt(d2) cross term of the reference is dropped
//          (relative contribution <= eps/z <= 1e-5 for interior targets).
// Phase 3: cross-warp reduction in SMEM, rim passthrough select, store.
// ---------------------------------------------------------------------------
__global__ void __launch_bounds__(1024, 1) fused_kernel(
    const float* __restrict__ b, float* __restrict__ out)
{
    extern __shared__ float4 ent[];          // CAP entries, 147456 B dynamic
    __shared__ int   cnts[RES];
    __shared__ int   offs[RES];
    __shared__ int   sK;
    __shared__ float red[NWARPS * 64];

    const int tid  = threadIdx.x;
    const int wid  = tid >> 5;
    const int lane = tid & 31;

    // ---------------- Phase 1: compaction ----------------
    // Pass 1: per-row positive counts (warp w owns rows 3w..3w+2)
    {
        const int r0 = wid * 3;
        #pragma unroll
        for (int rr = 0; rr < 3; rr++) {
            const int row = r0 + rr;
            int c = 0;
            #pragma unroll
            for (int s = 0; s < 3; s++) {
                float v = b[row * RES + s * 32 + lane];
                c += __popc(__ballot_sync(0xffffffffu, v > 0.0f));
            }
            if (lane == 0) cnts[row] = c;
        }
    }
    __syncthreads();

    // Exclusive prefix over 96 row counts (warp 0, shuffle scan)
    if (wid == 0) {
        int a0 = cnts[lane], a1 = cnts[lane + 32], a2 = cnts[lane + 64];
        int s0 = a0, s1 = a1, s2 = a2;
        #pragma unroll
        for (int d = 1; d < 32; d <<= 1) {
            int t0 = __shfl_up_sync(0xffffffffu, s0, d); if (lane >= d) s0 += t0;
            int t1 = __shfl_up_sync(0xffffffffu, s1, d); if (lane >= d) s1 += t1;
            int t2 = __shfl_up_sync(0xffffffffu, s2, d); if (lane >= d) s2 += t2;
        }
        int tot0 = __shfl_sync(0xffffffffu, s0, 31);
        s1 += tot0;
        int tot1 = __shfl_sync(0xffffffffu, s1, 31);
        s2 += tot1;
        offs[lane]      = s0 - a0;
        offs[lane + 32] = s1 - a1;
        offs[lane + 64] = s2 - a2;
        if (lane == 31) sK = s2;
    }
    __syncthreads();

    // Pass 2: scatter compacted entries (input is now L1-hot)
    {
        const int r0 = wid * 3;
        #pragma unroll
        for (int rr = 0; rr < 3; rr++) {
            const int row = r0 + rr;
            int p = offs[row];
            #pragma unroll
            for (int s = 0; s < 3; s++) {
                const int col = s * 32 + lane;
                float v = b[row * RES + col];
                unsigned m = __ballot_sync(0xffffffffu, v > 0.0f);
                if (v > 0.0f) {
                    int pos = p + __popc(m & ((1u << lane) - 1u));
                    ent[pos] = make_float4((float)row, (float)col, v, 0.0f);
                }
                p += __popc(m);
            }
        }
    }
    __syncthreads();

    // ---------------- Phase 2: potential ----------------
    const int i0  = (blockIdx.x / 3) * 2;          // first of two target rows
    const int jb  = (blockIdx.x % 3) * 32;
    const int j   = jb + lane;

    const float fi0 = (float)i0;
    const float fj  = (float)j;

    const float dic0 = fi0 - CENTERF;
    const float dic1 = dic0 + 1.0f;
    const float djc  = fj - CENTERF;
    const float r2_0 = dic0 * dic0 + djc * djc;    // exact integers
    const float r2_1 = dic1 * dic1 + djc * djc;
    const float z0 = CENTERF - sqrtf(r2_0) + EPSF;
    const float z1 = CENTERF - sqrtf(r2_1) + EPSF;
    const float c00 = fmaf(z0, z0, EPSF * EPSF);
    // Kc = 1 + (z1^2 - z0^2), computed in double to avoid cancellation error
    const float Kc = (float)(1.0 + ((double)z1 * (double)z1 - (double)z0 * (double)z0));

    const bool rim0 = (r2_0 >= RIM2);
    const bool rim1 = (r2_1 >= RIM2);
    // block-uniform: every warp sees the same lane->target mapping
    const bool allrim = __all_sync(0xffffffffu, rim0 && rim1);

    const int K = sK;
    float acc0 = 0.0f, acc1 = 0.0f;

    if (!allrim) {
        #pragma unroll 4
        for (int idx = wid; idx < K; idx += NWARPS) {
            float4 e   = ent[idx];                 // broadcast LDS.128
            float dj   = fj  - e.y;
            float di0  = fi0 - e.x;
            float s0   = fmaf(dj,  dj,  c00);
            float den0 = fmaf(di0, di0, s0);
            float t    = fmaf(di0, 2.0f, Kc);
            float den1 = den0 + t;
            float inv0, inv1;
            asm("rcp.approx.ftz.f32 %0, %1;" : "=f"(inv0) : "f"(den0));
            asm("rcp.approx.ftz.f32 %0, %1;" : "=f"(inv1) : "f"(den1));
            acc0 = fmaf(e.z, inv0, acc0);
            acc1 = fmaf(e.z, inv1, acc1);
        }
    }

    red[wid * 64 + lane]      = acc0;
    red[wid * 64 + 32 + lane] = acc1;
    __syncthreads();

    // ---------------- Phase 3: reduce + store ----------------
    if (tid < 64) {
        const int k = tid >> 5;                    // which of the two i-rows
        const int l = tid & 31;
        float s = 0.0f;
        #pragma unroll
        for (int w = 0; w < NWARPS; w++) s += red[w * 64 + k * 32 + l];

        const int ii = i0 + k;
        const int jj = jb + l;
        const float fii = (float)ii - CENTERF;
        const float fjj = (float)jj - CENTERF;
        const float r2  = fii * fii + fjj * fjj;
        const float bv  = b[ii * RES + jj];
        out[ii * RES + jj] = (r2 >= RIM2) ? bv : s;
    }
}

// ---------------------------------------------------------------------------
extern "C" void kernel_launch(void* const* d_in, const int* in_sizes, int n_in,
                              void* d_out, int out_size) {
    (void)in_sizes; (void)n_in; (void)out_size;
    const float* b   = (const float*)d_in[0];
    float*       out = (float*)d_out;

    const int smem_bytes = CAP * (int)sizeof(float4);  // 147456
    cudaFuncSetAttribute(fused_kernel,
                         cudaFuncAttributeMaxDynamicSharedMemorySize, smem_bytes);

    fused_kernel<<<144, 1024, smem_bytes>>>(b, out);
}